// round 1
// baseline (speedup 1.0000x reference)
#include <cuda_runtime.h>
#include <cstdint>

#define NTOK 16384
#define HDIM 1024
#define MDIM 512
#define NEXP 8
#define MAX_TILES 144

// ---------------- scratch (no allocations allowed) ----------------
__device__ float g_h[NTOK * MDIM];        // 32 MB relu(X@w1+b1)
__device__ int   g_idx[NTOK];
__device__ int   g_counts[NEXP];
__device__ int   g_base[NEXP];
__device__ int   g_cursor[NEXP];
__device__ int   g_perm[NTOK];
__device__ int   g_tile_e[MAX_TILES];
__device__ int   g_tile_r[MAX_TILES];
__device__ int   g_tile_n[MAX_TILES];
__device__ int   g_numtiles;

// ---------------- init (must run every launch for graph replay determinism) ----
__global__ void k_init() {
    int t = threadIdx.x;
    if (t < NEXP) { g_counts[t] = 0; g_cursor[t] = 0; }
}

// ---------------- gemm1: g_h = relu(X @ w1 + b1)   [16384x1024]@[1024x512] ----
__global__ __launch_bounds__(256) void k_gemm1(const float* __restrict__ X,
                                               const float* __restrict__ W,
                                               const float* __restrict__ b1) {
    __shared__ float As[2][8][128];
    __shared__ float Bs[2][8][128];

    const int tid  = threadIdx.x;
    const int row0 = blockIdx.x * 128;
    const int col0 = blockIdx.y * 128;
    const int tx   = tid & 15;
    const int ty   = tid >> 4;

    const int ar = tid >> 1;          // A load row 0..127
    const int ak = (tid & 1) * 4;     // A load k sub 0 or 4
    const int bk = tid >> 5;          // B load k 0..7
    const int bc = (tid & 31) * 4;    // B load col 0..124

    const float* Aptr = X + (size_t)(row0 + ar) * HDIM + ak;
    const float* Bptr = W + (size_t)bk * MDIM + col0 + bc;

    float acc[8][8];
#pragma unroll
    for (int i = 0; i < 8; i++)
#pragma unroll
        for (int j = 0; j < 8; j++) acc[i][j] = 0.0f;

    // preload tile 0
    float4 a4 = *(const float4*)(Aptr);
    float4 b4 = *(const float4*)(Bptr);
    As[0][ak + 0][ar] = a4.x; As[0][ak + 1][ar] = a4.y;
    As[0][ak + 2][ar] = a4.z; As[0][ak + 3][ar] = a4.w;
    *(float4*)&Bs[0][bk][bc] = b4;
    __syncthreads();

    const int NT = HDIM / 8;  // 128
    for (int t = 0; t < NT; t++) {
        const int buf = t & 1, nbuf = buf ^ 1;
        if (t + 1 < NT) {
            a4 = *(const float4*)(Aptr + (t + 1) * 8);
            b4 = *(const float4*)(Bptr + (size_t)(t + 1) * 8 * MDIM);
        }
#pragma unroll
        for (int kk = 0; kk < 8; kk++) {
            float4 av0 = *(const float4*)&As[buf][kk][ty * 8];
            float4 av1 = *(const float4*)&As[buf][kk][ty * 8 + 4];
            float4 bv0 = *(const float4*)&Bs[buf][kk][tx * 8];
            float4 bv1 = *(const float4*)&Bs[buf][kk][tx * 8 + 4];
            float a[8] = {av0.x, av0.y, av0.z, av0.w, av1.x, av1.y, av1.z, av1.w};
            float bb[8] = {bv0.x, bv0.y, bv0.z, bv0.w, bv1.x, bv1.y, bv1.z, bv1.w};
#pragma unroll
            for (int i = 0; i < 8; i++)
#pragma unroll
                for (int j = 0; j < 8; j++) acc[i][j] = fmaf(a[i], bb[j], acc[i][j]);
        }
        if (t + 1 < NT) {
            As[nbuf][ak + 0][ar] = a4.x; As[nbuf][ak + 1][ar] = a4.y;
            As[nbuf][ak + 2][ar] = a4.z; As[nbuf][ak + 3][ar] = a4.w;
            *(float4*)&Bs[nbuf][bk][bc] = b4;
        }
        __syncthreads();
    }

#pragma unroll
    for (int i = 0; i < 8; i++) {
        const int r = row0 + ty * 8 + i;
        float* out = g_h + (size_t)r * MDIM + col0 + tx * 8;
#pragma unroll
        for (int j = 0; j < 8; j++) {
            float v = acc[i][j] + b1[col0 + tx * 8 + j];
            out[j] = v > 0.0f ? v : 0.0f;
        }
    }
}

// ---------------- scores + argmax + counts ----------------
__global__ __launch_bounds__(256) void k_scores(const float* __restrict__ w2,
                                                const float* __restrict__ b2) {
    __shared__ float sw2t[NEXP * MDIM];  // transposed: [e][m], conflict-free
    for (int i = threadIdx.x; i < MDIM * NEXP; i += 256) {
        int m = i / NEXP, e = i % NEXP;
        sw2t[e * MDIM + m] = w2[i];
    }
    __syncthreads();

    const int warp = threadIdx.x >> 5;
    const int lane = threadIdx.x & 31;
    const int t = blockIdx.x * 8 + warp;

    const float* hrow = g_h + (size_t)t * MDIM;
    float s[NEXP];
#pragma unroll
    for (int e = 0; e < NEXP; e++) s[e] = 0.0f;

    for (int m = lane; m < MDIM; m += 32) {
        float hv = hrow[m];
#pragma unroll
        for (int e = 0; e < NEXP; e++) s[e] = fmaf(hv, sw2t[e * MDIM + m], s[e]);
    }
#pragma unroll
    for (int e = 0; e < NEXP; e++)
#pragma unroll
        for (int off = 16; off; off >>= 1)
            s[e] += __shfl_xor_sync(0xffffffffu, s[e], off);

    if (lane == 0) {
        int best = 0;
        float bv = s[0] + b2[0];
#pragma unroll
        for (int e = 1; e < NEXP; e++) {
            float v = s[e] + b2[e];
            if (v > bv) { bv = v; best = e; }   // strict > : first-max like jnp.argmax
        }
        g_idx[t] = best;
        atomicAdd(&g_counts[best], 1);
    }
}

// ---------------- scan: bases + tile descriptors ----------------
__global__ void k_scan() {
    int s = 0;
    for (int e = 0; e < NEXP; e++) { g_base[e] = s; s += g_counts[e]; }
    int nt = 0;
    for (int e = 0; e < NEXP; e++) {
        int c = g_counts[e];
        for (int r = 0; r < c; r += 128) {
            g_tile_e[nt] = e;
            g_tile_r[nt] = g_base[e] + r;
            g_tile_n[nt] = (c - r) < 128 ? (c - r) : 128;
            nt++;
        }
    }
    g_numtiles = nt;
}

// ---------------- fill grouped permutation ----------------
__global__ void k_fill() {
    int t = blockIdx.x * 256 + threadIdx.x;
    if (t < NTOK) {
        int e = g_idx[t];
        int r = atomicAdd(&g_cursor[e], 1);
        g_perm[g_base[e] + r] = t;
    }
}

// ---------------- grouped expert GEMM: out[tok] = X[tok] @ W[e] + b[e] --------
__global__ __launch_bounds__(256) void k_gemm2(const float* __restrict__ X,
                                               const float* __restrict__ eW,
                                               const float* __restrict__ eb,
                                               float* __restrict__ out) {
    const int tile = blockIdx.x;
    if (tile >= g_numtiles) return;

    __shared__ float As[2][8][128];
    __shared__ float Bs[2][8][128];
    __shared__ int   tk[128];

    const int e     = g_tile_e[tile];
    const int grs   = g_tile_r[tile];
    const int nrows = g_tile_n[tile];
    const int col0  = blockIdx.y * 128;

    const int tid = threadIdx.x;
    const int tx  = tid & 15;
    const int ty  = tid >> 4;

    const int ar = tid >> 1;
    const int ak = (tid & 1) * 4;
    const int bk = tid >> 5;
    const int bc = (tid & 31) * 4;

    // gathered A row: clamp invalid rows to segment start (loads safe, stores guarded)
    const int gi  = grs + (ar < nrows ? ar : 0);
    const int tok = g_perm[gi];
    if ((tid & 1) == 0) tk[ar] = tok;

    const float* Aptr = X + (size_t)tok * HDIM + ak;
    const float* Bptr = eW + ((size_t)e << 20) + (size_t)bk * HDIM + col0 + bc;

    float acc[8][8];
#pragma unroll
    for (int i = 0; i < 8; i++)
#pragma unroll
        for (int j = 0; j < 8; j++) acc[i][j] = 0.0f;

    float4 a4 = *(const float4*)(Aptr);
    float4 b4 = *(const float4*)(Bptr);
    As[0][ak + 0][ar] = a4.x; As[0][ak + 1][ar] = a4.y;
    As[0][ak + 2][ar] = a4.z; As[0][ak + 3][ar] = a4.w;
    *(float4*)&Bs[0][bk][bc] = b4;
    __syncthreads();

    const int NT = HDIM / 8;  // 128
    for (int t = 0; t < NT; t++) {
        const int buf = t & 1, nbuf = buf ^ 1;
        if (t + 1 < NT) {
            a4 = *(const float4*)(Aptr + (t + 1) * 8);
            b4 = *(const float4*)(Bptr + (size_t)(t + 1) * 8 * HDIM);
        }
#pragma unroll
        for (int kk = 0; kk < 8; kk++) {
            float4 av0 = *(const float4*)&As[buf][kk][ty * 8];
            float4 av1 = *(const float4*)&As[buf][kk][ty * 8 + 4];
            float4 bv0 = *(const float4*)&Bs[buf][kk][tx * 8];
            float4 bv1 = *(const float4*)&Bs[buf][kk][tx * 8 + 4];
            float a[8] = {av0.x, av0.y, av0.z, av0.w, av1.x, av1.y, av1.z, av1.w};
            float bb[8] = {bv0.x, bv0.y, bv0.z, bv0.w, bv1.x, bv1.y, bv1.z, bv1.w};
#pragma unroll
            for (int i = 0; i < 8; i++)
#pragma unroll
                for (int j = 0; j < 8; j++) acc[i][j] = fmaf(a[i], bb[j], acc[i][j]);
        }
        if (t + 1 < NT) {
            As[nbuf][ak + 0][ar] = a4.x; As[nbuf][ak + 1][ar] = a4.y;
            As[nbuf][ak + 2][ar] = a4.z; As[nbuf][ak + 3][ar] = a4.w;
            *(float4*)&Bs[nbuf][bk][bc] = b4;
        }
        __syncthreads();
    }

    const float* bias = eb + (size_t)e * HDIM + col0 + tx * 8;
#pragma unroll
    for (int i = 0; i < 8; i++) {
        const int r = ty * 8 + i;
        if (r < nrows) {
            const int t2 = tk[r];
            float* orow = out + (size_t)t2 * HDIM + col0 + tx * 8;
#pragma unroll
            for (int j = 0; j < 8; j++) orow[j] = acc[i][j] + bias[j];
        }
    }
}

// ---------------- launch ----------------
extern "C" void kernel_launch(void* const* d_in, const int* in_sizes, int n_in,
                              void* d_out, int out_size) {
    const float* X  = (const float*)d_in[0];  // (4,4096,1024)
    const float* w1 = (const float*)d_in[1];  // (1024,512)
    const float* b1 = (const float*)d_in[2];  // (512)
    const float* w2 = (const float*)d_in[3];  // (512,8)
    const float* b2 = (const float*)d_in[4];  // (8)
    const float* eW = (const float*)d_in[5];  // (8,1024,1024)
    const float* eb = (const float*)d_in[6];  // (8,1024)
    float* out = (float*)d_out;               // (4,4096,1024)

    k_init<<<1, 32>>>();
    k_gemm1<<<dim3(NTOK / 128, MDIM / 128), 256>>>(X, w1, b1);
    k_scores<<<NTOK / 8, 256>>>(w2, b2);
    k_scan<<<1, 1>>>();
    k_fill<<<NTOK / 256, 256>>>();
    k_gemm2<<<dim3(MAX_TILES, HDIM / 128), 256>>>(X, eW, eb, out);
}

// round 4
// speedup vs baseline: 2.2744x; 2.2744x over previous
#include <cuda_runtime.h>
#include <cuda_fp16.h>
#include <cstdint>

#define NTOK 16384
#define HDIM 1024
#define MDIM 512
#define NEXP 8
#define MAX_TILES 144
#define NC 32                 // K chunks of 32
#define STAGE_B 40960         // 4 tiles * 128 rows * 80 bytes
#define TILE_PB 10240         // one padded tile: 128 * 80B
#define ROW_PB 80             // padded row bytes (32 fp16 + 8 pad)

// ---------------- scratch ----------------
__device__ float  g_h[NTOK * MDIM];
__device__ __half g_X1[NTOK * HDIM];
__device__ __half g_X2[NTOK * HDIM];
__device__ __half g_W1a[MDIM * HDIM];
__device__ __half g_W1b[MDIM * HDIM];
__device__ __half g_W2a[NEXP * HDIM * HDIM];
__device__ __half g_W2b[NEXP * HDIM * HDIM];
__device__ int g_idx[NTOK];
__device__ int g_counts[NEXP];
__device__ int g_base[NEXP];
__device__ int g_cursor[NEXP];
__device__ int g_perm[NTOK];
__device__ int g_tile_e[MAX_TILES];
__device__ int g_tile_r[MAX_TILES];
__device__ int g_tile_n[MAX_TILES];
__device__ int g_numtiles;

// ---------------- helpers ----------------
__device__ __forceinline__ uint32_t smem_u32(const void* p) {
    uint32_t a;
    asm("{ .reg .u64 t; cvta.to.shared.u64 t, %1; cvt.u32.u64 %0, t; }" : "=r"(a) : "l"(p));
    return a;
}
__device__ __forceinline__ void cp16(uint32_t s, const void* g) {
    asm volatile("cp.async.cg.shared.global [%0], [%1], 16;" :: "r"(s), "l"(g));
}
#define CP_COMMIT() asm volatile("cp.async.commit_group;" ::: "memory")
#define CP_WAIT1()  asm volatile("cp.async.wait_group 1;" ::: "memory")
__device__ __forceinline__ void ldsm4(uint32_t r[4], uint32_t a) {
    asm volatile("ldmatrix.sync.aligned.m8n8.x4.shared.b16 {%0,%1,%2,%3}, [%4];"
                 : "=r"(r[0]), "=r"(r[1]), "=r"(r[2]), "=r"(r[3]) : "r"(a));
}
__device__ __forceinline__ void mma16816(float c[4], const uint32_t a[4], const uint32_t b[2]) {
    asm volatile(
        "mma.sync.aligned.m16n8k16.row.col.f32.f16.f16.f32 "
        "{%0,%1,%2,%3}, {%4,%5,%6,%7}, {%8,%9}, {%0,%1,%2,%3};"
        : "+f"(c[0]), "+f"(c[1]), "+f"(c[2]), "+f"(c[3])
        : "r"(a[0]), "r"(a[1]), "r"(a[2]), "r"(a[3]), "r"(b[0]), "r"(b[1]));
}

// ---------------- init ----------------
__global__ void k_init() {
    int t = threadIdx.x;
    if (t < NEXP) { g_counts[t] = 0; g_cursor[t] = 0; }
}

// ---------------- X -> fp16 2-way split ----------------
__global__ __launch_bounds__(256) void k_convA(const float* __restrict__ X) {
    int i = blockIdx.x * 256 + threadIdx.x;  // float4 index
    float4 v = ((const float4*)X)[i];
    float xs[4] = {v.x, v.y, v.z, v.w};
    __align__(8) __half a1[4], a2[4];
#pragma unroll
    for (int c = 0; c < 4; c++) {
        float x = xs[c];
        __half h1 = __float2half_rn(x);
        float r = x - __half2float(h1);
        a1[c] = h1;
        a2[c] = __float2half_rn(r);
    }
    ((uint2*)g_X1)[i] = *(uint2*)a1;
    ((uint2*)g_X2)[i] = *(uint2*)a2;
}

// ---------------- w1 [K][N] -> [N][K] fp16 x2 ----------------
__global__ void k_convW1(const float* __restrict__ src) {
    __shared__ float t[32][33];
    int n0 = blockIdx.x * 32, k0 = blockIdx.y * 32;
    int tx = threadIdx.x, ty = threadIdx.y;
#pragma unroll
    for (int j = 0; j < 4; j++)
        t[ty + 8 * j][tx] = src[(size_t)(k0 + ty + 8 * j) * MDIM + n0 + tx];
    __syncthreads();
#pragma unroll
    for (int j = 0; j < 4; j++) {
        int rr = ty + 8 * j;
        float x = t[tx][rr];
        __half h1 = __float2half_rn(x);
        float r = x - __half2float(h1);
        size_t o = (size_t)(n0 + rr) * HDIM + k0 + tx;
        g_W1a[o] = h1;
        g_W1b[o] = __float2half_rn(r);
    }
}

// ---------------- expert_W [E][K][N] -> [E][N][K] fp16 x2 ----------------
__global__ void k_convW2(const float* __restrict__ src) {
    __shared__ float t[32][33];
    int e = blockIdx.z;
    const float* s = src + ((size_t)e << 20);
    __half* d1 = g_W2a + ((size_t)e << 20);
    __half* d2 = g_W2b + ((size_t)e << 20);
    int n0 = blockIdx.x * 32, k0 = blockIdx.y * 32;
    int tx = threadIdx.x, ty = threadIdx.y;
#pragma unroll
    for (int j = 0; j < 4; j++)
        t[ty + 8 * j][tx] = s[(size_t)(k0 + ty + 8 * j) * HDIM + n0 + tx];
    __syncthreads();
#pragma unroll
    for (int j = 0; j < 4; j++) {
        int rr = ty + 8 * j;
        float x = t[tx][rr];
        __half h1 = __float2half_rn(x);
        float r = x - __half2float(h1);
        size_t o = (size_t)(n0 + rr) * HDIM + k0 + tx;
        d1[o] = h1;
        d2[o] = __float2half_rn(r);
    }
}

// ---------------- fused 3-pass fp16 GEMM (mma.sync) ----------------
// C[128x128] = (A1+A2)[128xK] @ (B1+B2)^T[K x 128] via A1B1 + A2B1 + A1B2
template <bool GATHER>
__global__ __launch_bounds__(256) void k_gemm_mma(const float* __restrict__ biasg,
                                                  float* __restrict__ outg) {
    __shared__ float sbias[128];
    __shared__ int tks[128];
    extern __shared__ char dsm[];
    const uint32_t sb = smem_u32(dsm);

    const int tid = threadIdx.x;
    const int wid = tid >> 5;
    const int lane = tid & 31;
    const int warp_m = wid >> 2;   // 0..1
    const int warp_n = wid & 3;    // 0..3

    int row0 = 0, nrows = 128, col0 = blockIdx.y * 128;
    const __half *A1, *A2, *B1, *B2;
    if (GATHER) {
        const int tile = blockIdx.x;
        if (tile >= g_numtiles) return;
        const int e = g_tile_e[tile];
        const int grs = g_tile_r[tile];
        nrows = g_tile_n[tile];
        if (tid < 128) {
            tks[tid] = g_perm[grs + (tid < nrows ? tid : 0)];
            sbias[tid] = biasg[(size_t)e * HDIM + col0 + tid];
        }
        A1 = g_X1; A2 = g_X2;
        B1 = g_W2a + ((size_t)e << 20) + (size_t)col0 * HDIM;
        B2 = g_W2b + ((size_t)e << 20) + (size_t)col0 * HDIM;
    } else {
        row0 = blockIdx.x * 128;
        if (tid < 128) sbias[tid] = biasg[col0 + tid];
        A1 = g_X1; A2 = g_X2;
        B1 = g_W1a + (size_t)col0 * HDIM;
        B2 = g_W1b + (size_t)col0 * HDIM;
    }
    __syncthreads();

    // per-thread cp.async mapping: 8 chunks of 16B per stage
    int c_tile[8], c_row[8], c_seg[8];
#pragma unroll
    for (int i = 0; i < 8; i++) {
        int cid = tid + i * 256;
        c_tile[i] = cid >> 9;
        int c2 = cid & 511;
        c_row[i] = c2 >> 2;
        c_seg[i] = c2 & 3;
    }

    auto issue = [&](int buf, int kbase) {
#pragma unroll
        for (int i = 0; i < 8; i++) {
            const int tile = c_tile[i], row = c_row[i], seg = c_seg[i];
            uint32_t sa = sb + buf * STAGE_B + tile * TILE_PB + row * ROW_PB + seg * 16;
            const __half* src;
            int grow;
            if (tile == 0)      { src = A1; grow = GATHER ? tks[row] : row0 + row; }
            else if (tile == 1) { src = A2; grow = GATHER ? tks[row] : row0 + row; }
            else if (tile == 2) { src = B1; grow = row; }
            else                { src = B2; grow = row; }
            cp16(sa, src + (size_t)grow * HDIM + kbase + seg * 8);
        }
    };

    float acc[4][4][4];
#pragma unroll
    for (int mi = 0; mi < 4; mi++)
#pragma unroll
        for (int ni = 0; ni < 4; ni++)
#pragma unroll
            for (int k = 0; k < 4; k++) acc[mi][ni][k] = 0.0f;

    issue(0, 0);  CP_COMMIT();
    issue(1, 32); CP_COMMIT();

    const int lm = lane & 15, lh = lane >> 4;
    const uint32_t a_off = (uint32_t)((warp_m * 64 + lm) * ROW_PB + lh * 16);
    const uint32_t b_off = (uint32_t)((warp_n * 32 + lm) * ROW_PB + lh * 16);

    for (int c = 0; c < NC; c++) {
        CP_WAIT1();
        __syncthreads();
        const int buf = c & 1;
        const uint32_t sA1 = sb + buf * STAGE_B;
        const uint32_t sA2 = sA1 + TILE_PB;
        const uint32_t sB1 = sA1 + 2 * TILE_PB;
        const uint32_t sB2 = sA1 + 3 * TILE_PB;

#pragma unroll
        for (int kh = 0; kh < 2; kh++) {
            uint32_t a1[4][4], a2[4][4], b1f[4][2], b2f[4][2];
#pragma unroll
            for (int mi = 0; mi < 4; mi++) {
                ldsm4(a1[mi], sA1 + a_off + mi * (16 * ROW_PB) + kh * 32);
                ldsm4(a2[mi], sA2 + a_off + mi * (16 * ROW_PB) + kh * 32);
            }
#pragma unroll
            for (int nt = 0; nt < 2; nt++) {
                uint32_t r[4];
                ldsm4(r, sB1 + b_off + nt * (16 * ROW_PB) + kh * 32);
                b1f[nt * 2][0] = r[0]; b1f[nt * 2][1] = r[2];
                b1f[nt * 2 + 1][0] = r[1]; b1f[nt * 2 + 1][1] = r[3];
                ldsm4(r, sB2 + b_off + nt * (16 * ROW_PB) + kh * 32);
                b2f[nt * 2][0] = r[0]; b2f[nt * 2][1] = r[2];
                b2f[nt * 2 + 1][0] = r[1]; b2f[nt * 2 + 1][1] = r[3];
            }
#pragma unroll
            for (int mi = 0; mi < 4; mi++)
#pragma unroll
                for (int ni = 0; ni < 4; ni++) {
                    mma16816(acc[mi][ni], a1[mi], b1f[ni]);
                    mma16816(acc[mi][ni], a2[mi], b1f[ni]);
                    mma16816(acc[mi][ni], a1[mi], b2f[ni]);
                }
        }
        __syncthreads();
        if (c + 2 < NC) issue(buf, (c + 2) * 32);
        CP_COMMIT();
    }

    // epilogue
    const int rbase = warp_m * 64 + (lane >> 2);
    const int cbase = warp_n * 32 + (lane & 3) * 2;
#pragma unroll
    for (int mi = 0; mi < 4; mi++) {
#pragma unroll
        for (int ni = 0; ni < 4; ni++) {
            const int r0 = rbase + mi * 16;
            const int cc = cbase + ni * 8;
            float v00 = acc[mi][ni][0] + sbias[cc];
            float v01 = acc[mi][ni][1] + sbias[cc + 1];
            float v10 = acc[mi][ni][2] + sbias[cc];
            float v11 = acc[mi][ni][3] + sbias[cc + 1];
            if (GATHER) {
                if (r0 < nrows) {
                    float* p = outg + (size_t)tks[r0] * HDIM + col0 + cc;
                    *(float2*)p = make_float2(v00, v01);
                }
                if (r0 + 8 < nrows) {
                    float* p = outg + (size_t)tks[r0 + 8] * HDIM + col0 + cc;
                    *(float2*)p = make_float2(v10, v11);
                }
            } else {
                float* p0 = g_h + (size_t)(row0 + r0) * MDIM + col0 + cc;
                float* p1 = g_h + (size_t)(row0 + r0 + 8) * MDIM + col0 + cc;
                *(float2*)p0 = make_float2(fmaxf(v00, 0.f), fmaxf(v01, 0.f));
                *(float2*)p1 = make_float2(fmaxf(v10, 0.f), fmaxf(v11, 0.f));
            }
        }
    }
}

// ---------------- scores + argmax + counts ----------------
__global__ __launch_bounds__(256) void k_scores(const float* __restrict__ w2,
                                                const float* __restrict__ b2) {
    __shared__ float sw2t[NEXP * MDIM];
    for (int i = threadIdx.x; i < MDIM * NEXP; i += 256) {
        int m = i / NEXP, e = i % NEXP;
        sw2t[e * MDIM + m] = w2[i];
    }
    __syncthreads();
    const int warp = threadIdx.x >> 5, lane = threadIdx.x & 31;
    const int t = blockIdx.x * 8 + warp;
    const float* hrow = g_h + (size_t)t * MDIM;
    float s[NEXP];
#pragma unroll
    for (int e = 0; e < NEXP; e++) s[e] = 0.0f;
    for (int m = lane; m < MDIM; m += 32) {
        float hv = hrow[m];
#pragma unroll
        for (int e = 0; e < NEXP; e++) s[e] = fmaf(hv, sw2t[e * MDIM + m], s[e]);
    }
#pragma unroll
    for (int e = 0; e < NEXP; e++)
#pragma unroll
        for (int off = 16; off; off >>= 1) s[e] += __shfl_xor_sync(0xffffffffu, s[e], off);
    if (lane == 0) {
        int best = 0;
        float bv = s[0] + b2[0];
#pragma unroll
        for (int e = 1; e < NEXP; e++) {
            float v = s[e] + b2[e];
            if (v > bv) { bv = v; best = e; }
        }
        g_idx[t] = best;
        atomicAdd(&g_counts[best], 1);
    }
}

// ---------------- scan + fill ----------------
__global__ void k_scan() {
    int s = 0;
    for (int e = 0; e < NEXP; e++) { g_base[e] = s; s += g_counts[e]; }
    int nt = 0;
    for (int e = 0; e < NEXP; e++) {
        int c = g_counts[e];
        for (int r = 0; r < c; r += 128) {
            g_tile_e[nt] = e;
            g_tile_r[nt] = g_base[e] + r;
            g_tile_n[nt] = (c - r) < 128 ? (c - r) : 128;
            nt++;
        }
    }
    g_numtiles = nt;
}
__global__ void k_fill() {
    int t = blockIdx.x * 256 + threadIdx.x;
    if (t < NTOK) {
        int e = g_idx[t];
        int r = atomicAdd(&g_cursor[e], 1);
        g_perm[g_base[e] + r] = t;
    }
}

// ---------------- launch ----------------
extern "C" void kernel_launch(void* const* d_in, const int* in_sizes, int n_in,
                              void* d_out, int out_size) {
    const float* X  = (const float*)d_in[0];
    const float* w1 = (const float*)d_in[1];
    const float* b1 = (const float*)d_in[2];
    const float* w2 = (const float*)d_in[3];
    const float* b2 = (const float*)d_in[4];
    const float* eW = (const float*)d_in[5];
    const float* eb = (const float*)d_in[6];
    float* out = (float*)d_out;

    const int DSM = 2 * STAGE_B;  // 81920
    cudaFuncSetAttribute(k_gemm_mma<false>, cudaFuncAttributeMaxDynamicSharedMemorySize, DSM);
    cudaFuncSetAttribute(k_gemm_mma<true>,  cudaFuncAttributeMaxDynamicSharedMemorySize, DSM);

    k_init<<<1, 32>>>();
    k_convA<<<NTOK * HDIM / 1024, 256>>>(X);
    k_convW1<<<dim3(MDIM / 32, HDIM / 32, 1), dim3(32, 8)>>>(w1);
    k_convW2<<<dim3(HDIM / 32, HDIM / 32, NEXP), dim3(32, 8)>>>(eW);
    k_gemm_mma<false><<<dim3(NTOK / 128, MDIM / 128), 256, DSM>>>(b1, nullptr);
    k_scores<<<NTOK / 8, 256>>>(w2, b2);
    k_scan<<<1, 1>>>();
    k_fill<<<NTOK / 256, 256>>>();
    k_gemm_mma<true><<<dim3(MAX_TILES, HDIM / 128), 256, DSM>>>(eb, out);
}

// round 5
// speedup vs baseline: 2.7145x; 1.1935x over previous
#include <cuda_runtime.h>
#include <cuda_fp16.h>
#include <cstdint>

#define NTOK 16384
#define HDIM 1024
#define MDIM 512
#define NEXP 8
#define MAX_TILES 144
#define NC 32                 // K chunks of 32
#define TILE_PB 10240         // one padded tile: 128 rows * 80B
#define ROW_PB 80             // padded row bytes (32 fp16 + 8 pad)

// ---------------- scratch ----------------
__device__ float  g_h[NTOK * MDIM];
__device__ __half g_X1[NTOK * HDIM];
__device__ __half g_X2[NTOK * HDIM];
__device__ __half g_W1a[MDIM * HDIM];
__device__ __half g_W1b[MDIM * HDIM];
__device__ __half g_W2a[NEXP * HDIM * HDIM];
__device__ int g_idx[NTOK];
__device__ int g_counts[NEXP];
__device__ int g_base[NEXP];
__device__ int g_cursor[NEXP];
__device__ int g_perm[NTOK];
__device__ int g_tile_e[MAX_TILES];
__device__ int g_tile_r[MAX_TILES];
__device__ int g_tile_n[MAX_TILES];
__device__ int g_numtiles;

// ---------------- helpers ----------------
__device__ __forceinline__ uint32_t smem_u32(const void* p) {
    uint32_t a;
    asm("{ .reg .u64 t; cvta.to.shared.u64 t, %1; cvt.u32.u64 %0, t; }" : "=r"(a) : "l"(p));
    return a;
}
__device__ __forceinline__ void cp16(uint32_t s, const void* g) {
    asm volatile("cp.async.cg.shared.global [%0], [%1], 16;" :: "r"(s), "l"(g));
}
#define CP_COMMIT() asm volatile("cp.async.commit_group;" ::: "memory")
#define CP_WAIT1()  asm volatile("cp.async.wait_group 1;" ::: "memory")
__device__ __forceinline__ void ldsm4(uint32_t r[4], uint32_t a) {
    asm volatile("ldmatrix.sync.aligned.m8n8.x4.shared.b16 {%0,%1,%2,%3}, [%4];"
                 : "=r"(r[0]), "=r"(r[1]), "=r"(r[2]), "=r"(r[3]) : "r"(a));
}
__device__ __forceinline__ void mma16816(float c[4], const uint32_t a[4], const uint32_t b[2]) {
    asm volatile(
        "mma.sync.aligned.m16n8k16.row.col.f32.f16.f16.f32 "
        "{%0,%1,%2,%3}, {%4,%5,%6,%7}, {%8,%9}, {%0,%1,%2,%3};"
        : "+f"(c[0]), "+f"(c[1]), "+f"(c[2]), "+f"(c[3])
        : "r"(a[0]), "r"(a[1]), "r"(a[2]), "r"(a[3]), "r"(b[0]), "r"(b[1]));
}

// ---------------- init ----------------
__global__ void k_init() {
    int t = threadIdx.x;
    if (t < NEXP) { g_counts[t] = 0; g_cursor[t] = 0; }
}

// ---------------- X -> fp16 2-way split ----------------
__global__ __launch_bounds__(256) void k_convA(const float* __restrict__ X) {
    int i = blockIdx.x * 256 + threadIdx.x;  // float4 index
    float4 v = ((const float4*)X)[i];
    float xs[4] = {v.x, v.y, v.z, v.w};
    __align__(8) __half a1[4], a2[4];
#pragma unroll
    for (int c = 0; c < 4; c++) {
        float x = xs[c];
        __half h1 = __float2half_rn(x);
        float r = x - __half2float(h1);
        a1[c] = h1;
        a2[c] = __float2half_rn(r);
    }
    ((uint2*)g_X1)[i] = *(uint2*)a1;
    ((uint2*)g_X2)[i] = *(uint2*)a2;
}

// ---------------- w1 [K][N] -> [N][K] fp16 x2 (gating: full accuracy) --------
__global__ void k_convW1(const float* __restrict__ src) {
    __shared__ float t[32][33];
    int n0 = blockIdx.x * 32, k0 = blockIdx.y * 32;
    int tx = threadIdx.x, ty = threadIdx.y;
#pragma unroll
    for (int j = 0; j < 4; j++)
        t[ty + 8 * j][tx] = src[(size_t)(k0 + ty + 8 * j) * MDIM + n0 + tx];
    __syncthreads();
#pragma unroll
    for (int j = 0; j < 4; j++) {
        int rr = ty + 8 * j;
        float x = t[tx][rr];
        __half h1 = __float2half_rn(x);
        float r = x - __half2float(h1);
        size_t o = (size_t)(n0 + rr) * HDIM + k0 + tx;
        g_W1a[o] = h1;
        g_W1b[o] = __float2half_rn(r);
    }
}

// ---------------- expert_W [E][K][N] -> [E][N][K] fp16 single (rounded) ------
__global__ void k_convW2(const float* __restrict__ src) {
    __shared__ float t[32][33];
    int e = blockIdx.z;
    const float* s = src + ((size_t)e << 20);
    __half* d1 = g_W2a + ((size_t)e << 20);
    int n0 = blockIdx.x * 32, k0 = blockIdx.y * 32;
    int tx = threadIdx.x, ty = threadIdx.y;
#pragma unroll
    for (int j = 0; j < 4; j++)
        t[ty + 8 * j][tx] = s[(size_t)(k0 + ty + 8 * j) * HDIM + n0 + tx];
    __syncthreads();
#pragma unroll
    for (int j = 0; j < 4; j++) {
        int rr = ty + 8 * j;
        size_t o = (size_t)(n0 + rr) * HDIM + k0 + tx;
        d1[o] = __float2half_rn(t[tx][rr]);
    }
}

// ---------------- fused multi-pass fp16 GEMM (mma.sync) ----------------
// !GATHER (gating): C = a1b1 + a2b1 + a1b2  (4 tiles/stage)
//  GATHER (expert): C = a1b1 + a2b1        (3 tiles/stage)
template <bool GATHER>
__global__ __launch_bounds__(256) void k_gemm_mma(const float* __restrict__ biasg,
                                                  float* __restrict__ outg) {
    constexpr int NT = GATHER ? 3 : 4;            // tiles per stage
    constexpr int STAGE = NT * TILE_PB;
    constexpr int CH = NT * 2;                    // 16B chunks per thread per stage

    __shared__ float sbias[128];
    __shared__ int tks[128];
    extern __shared__ char dsm[];
    const uint32_t sb = smem_u32(dsm);

    const int tid = threadIdx.x;
    const int wid = tid >> 5;
    const int lane = tid & 31;
    const int warp_m = wid >> 2;   // 0..1
    const int warp_n = wid & 3;    // 0..3

    int row0 = 0, nrows = 128, col0 = blockIdx.y * 128;
    const __half *A1, *A2, *B1, *B2 = nullptr;
    if (GATHER) {
        const int tile = blockIdx.x;
        if (tile >= g_numtiles) return;
        const int e = g_tile_e[tile];
        const int grs = g_tile_r[tile];
        nrows = g_tile_n[tile];
        if (tid < 128) {
            tks[tid] = g_perm[grs + (tid < nrows ? tid : 0)];
            sbias[tid] = biasg[(size_t)e * HDIM + col0 + tid];
        }
        A1 = g_X1; A2 = g_X2;
        B1 = g_W2a + ((size_t)e << 20) + (size_t)col0 * HDIM;
    } else {
        row0 = blockIdx.x * 128;
        if (tid < 128) sbias[tid] = biasg[col0 + tid];
        A1 = g_X1; A2 = g_X2;
        B1 = g_W1a + (size_t)col0 * HDIM;
        B2 = g_W1b + (size_t)col0 * HDIM;
    }
    __syncthreads();

    // per-thread cp.async mapping: CH chunks of 16B per stage
    int c_tile[CH], c_row[CH], c_seg[CH];
#pragma unroll
    for (int i = 0; i < CH; i++) {
        int cid = tid + i * 256;
        c_tile[i] = cid >> 9;
        int c2 = cid & 511;
        c_row[i] = c2 >> 2;
        c_seg[i] = c2 & 3;
    }

    auto issue = [&](int buf, int kbase) {
#pragma unroll
        for (int i = 0; i < CH; i++) {
            const int tile = c_tile[i], row = c_row[i], seg = c_seg[i];
            uint32_t sa = sb + buf * STAGE + tile * TILE_PB + row * ROW_PB + seg * 16;
            const __half* src;
            int grow;
            if (tile == 0)      { src = A1; grow = GATHER ? tks[row] : row0 + row; }
            else if (tile == 1) { src = A2; grow = GATHER ? tks[row] : row0 + row; }
            else if (tile == 2) { src = B1; grow = row; }
            else                { src = B2; grow = row; }
            cp16(sa, src + (size_t)grow * HDIM + kbase + seg * 8);
        }
    };

    float acc[4][4][4];
#pragma unroll
    for (int mi = 0; mi < 4; mi++)
#pragma unroll
        for (int ni = 0; ni < 4; ni++)
#pragma unroll
            for (int k = 0; k < 4; k++) acc[mi][ni][k] = 0.0f;

    issue(0, 0);  CP_COMMIT();
    issue(1, 32); CP_COMMIT();

    const int lm = lane & 15, lh = lane >> 4;
    const uint32_t a_off = (uint32_t)((warp_m * 64 + lm) * ROW_PB + lh * 16);
    const uint32_t b_off = (uint32_t)((warp_n * 32 + lm) * ROW_PB + lh * 16);

    for (int c = 0; c < NC; c++) {
        CP_WAIT1();
        __syncthreads();
        const int buf = c & 1;
        const uint32_t sA1 = sb + buf * STAGE;
        const uint32_t sA2 = sA1 + TILE_PB;
        const uint32_t sB1 = sA1 + 2 * TILE_PB;
        const uint32_t sB2 = sA1 + 3 * TILE_PB;

#pragma unroll
        for (int kh = 0; kh < 2; kh++) {
            uint32_t a1[4][4], a2[4][4], b1f[4][2], b2f[4][2];
#pragma unroll
            for (int mi = 0; mi < 4; mi++) {
                ldsm4(a1[mi], sA1 + a_off + mi * (16 * ROW_PB) + kh * 32);
                ldsm4(a2[mi], sA2 + a_off + mi * (16 * ROW_PB) + kh * 32);
            }
#pragma unroll
            for (int nt = 0; nt < 2; nt++) {
                uint32_t r[4];
                ldsm4(r, sB1 + b_off + nt * (16 * ROW_PB) + kh * 32);
                b1f[nt * 2][0] = r[0]; b1f[nt * 2][1] = r[2];
                b1f[nt * 2 + 1][0] = r[1]; b1f[nt * 2 + 1][1] = r[3];
                if (!GATHER) {
                    ldsm4(r, sB2 + b_off + nt * (16 * ROW_PB) + kh * 32);
                    b2f[nt * 2][0] = r[0]; b2f[nt * 2][1] = r[2];
                    b2f[nt * 2 + 1][0] = r[1]; b2f[nt * 2 + 1][1] = r[3];
                }
            }
#pragma unroll
            for (int mi = 0; mi < 4; mi++)
#pragma unroll
                for (int ni = 0; ni < 4; ni++) {
                    mma16816(acc[mi][ni], a1[mi], b1f[ni]);
                    mma16816(acc[mi][ni], a2[mi], b1f[ni]);
                    if (!GATHER) mma16816(acc[mi][ni], a1[mi], b2f[ni]);
                }
        }
        __syncthreads();
        if (c + 2 < NC) issue(buf, (c + 2) * 32);
        CP_COMMIT();
    }

    // epilogue
    const int rbase = warp_m * 64 + (lane >> 2);
    const int cbase = warp_n * 32 + (lane & 3) * 2;
#pragma unroll
    for (int mi = 0; mi < 4; mi++) {
#pragma unroll
        for (int ni = 0; ni < 4; ni++) {
            const int r0 = rbase + mi * 16;
            const int cc = cbase + ni * 8;
            float v00 = acc[mi][ni][0] + sbias[cc];
            float v01 = acc[mi][ni][1] + sbias[cc + 1];
            float v10 = acc[mi][ni][2] + sbias[cc];
            float v11 = acc[mi][ni][3] + sbias[cc + 1];
            if (GATHER) {
                if (r0 < nrows) {
                    float* p = outg + (size_t)tks[r0] * HDIM + col0 + cc;
                    *(float2*)p = make_float2(v00, v01);
                }
                if (r0 + 8 < nrows) {
                    float* p = outg + (size_t)tks[r0 + 8] * HDIM + col0 + cc;
                    *(float2*)p = make_float2(v10, v11);
                }
            } else {
                float* p0 = g_h + (size_t)(row0 + r0) * MDIM + col0 + cc;
                float* p1 = g_h + (size_t)(row0 + r0 + 8) * MDIM + col0 + cc;
                *(float2*)p0 = make_float2(fmaxf(v00, 0.f), fmaxf(v01, 0.f));
                *(float2*)p1 = make_float2(fmaxf(v10, 0.f), fmaxf(v11, 0.f));
            }
        }
    }
}

// ---------------- scores + argmax + counts ----------------
__global__ __launch_bounds__(256) void k_scores(const float* __restrict__ w2,
                                                const float* __restrict__ b2) {
    __shared__ float sw2t[NEXP * MDIM];
    for (int i = threadIdx.x; i < MDIM * NEXP; i += 256) {
        int m = i / NEXP, e = i % NEXP;
        sw2t[e * MDIM + m] = w2[i];
    }
    __syncthreads();
    const int warp = threadIdx.x >> 5, lane = threadIdx.x & 31;
    const int t = blockIdx.x * 8 + warp;
    const float* hrow = g_h + (size_t)t * MDIM;
    float s[NEXP];
#pragma unroll
    for (int e = 0; e < NEXP; e++) s[e] = 0.0f;
    for (int m = lane; m < MDIM; m += 32) {
        float hv = hrow[m];
#pragma unroll
        for (int e = 0; e < NEXP; e++) s[e] = fmaf(hv, sw2t[e * MDIM + m], s[e]);
    }
#pragma unroll
    for (int e = 0; e < NEXP; e++)
#pragma unroll
        for (int off = 16; off; off >>= 1) s[e] += __shfl_xor_sync(0xffffffffu, s[e], off);
    if (lane == 0) {
        int best = 0;
        float bv = s[0] + b2[0];
#pragma unroll
        for (int e = 1; e < NEXP; e++) {
            float v = s[e] + b2[e];
            if (v > bv) { bv = v; best = e; }
        }
        g_idx[t] = best;
        atomicAdd(&g_counts[best], 1);
    }
}

// ---------------- scan + fill ----------------
__global__ void k_scan() {
    int s = 0;
    for (int e = 0; e < NEXP; e++) { g_base[e] = s; s += g_counts[e]; }
    int nt = 0;
    for (int e = 0; e < NEXP; e++) {
        int c = g_counts[e];
        for (int r = 0; r < c; r += 128) {
            g_tile_e[nt] = e;
            g_tile_r[nt] = g_base[e] + r;
            g_tile_n[nt] = (c - r) < 128 ? (c - r) : 128;
            nt++;
        }
    }
    g_numtiles = nt;
}
__global__ void k_fill() {
    int t = blockIdx.x * 256 + threadIdx.x;
    if (t < NTOK) {
        int e = g_idx[t];
        int r = atomicAdd(&g_cursor[e], 1);
        g_perm[g_base[e] + r] = t;
    }
}

// ---------------- launch ----------------
extern "C" void kernel_launch(void* const* d_in, const int* in_sizes, int n_in,
                              void* d_out, int out_size) {
    const float* X  = (const float*)d_in[0];
    const float* w1 = (const float*)d_in[1];
    const float* b1 = (const float*)d_in[2];
    const float* w2 = (const float*)d_in[3];
    const float* b2 = (const float*)d_in[4];
    const float* eW = (const float*)d_in[5];
    const float* eb = (const float*)d_in[6];
    float* out = (float*)d_out;

    const int DSM1 = 2 * 4 * TILE_PB;  // 81920
    const int DSM2 = 2 * 3 * TILE_PB;  // 61440
    cudaFuncSetAttribute(k_gemm_mma<false>, cudaFuncAttributeMaxDynamicSharedMemorySize, DSM1);
    cudaFuncSetAttribute(k_gemm_mma<true>,  cudaFuncAttributeMaxDynamicSharedMemorySize, DSM2);

    k_init<<<1, 32>>>();
    k_convA<<<NTOK * HDIM / 1024, 256>>>(X);
    k_convW1<<<dim3(MDIM / 32, HDIM / 32, 1), dim3(32, 8)>>>(w1);
    k_convW2<<<dim3(HDIM / 32, HDIM / 32, NEXP), dim3(32, 8)>>>(eW);
    k_gemm_mma<false><<<dim3(NTOK / 128, MDIM / 128), 256, DSM1>>>(b1, nullptr);
    k_scores<<<NTOK / 8, 256>>>(w2, b2);
    k_scan<<<1, 1>>>();
    k_fill<<<NTOK / 256, 256>>>();
    k_gemm_mma<true><<<dim3(MAX_TILES, HDIM / 128), 256, DSM2>>>(eb, out);
}